// round 10
// baseline (speedup 1.0000x reference)
#include <cuda_runtime.h>
#include <cuda_fp16.h>
#include <cstdint>

// FwFM second-order via mma.sync fp16 + cp.async double-buffered pipeline,
// persistent grid-stride CTAs (no wave quantization), single launch.
//   out[c] = sum_l x[l,c] * T[l,c],  T: A = X^T (M=cols), B = L^T (N=l).

#define KF 39
#define BD (8192 * 64)
#define NCOL 128             // columns per tile
#define NT (BD / NCOL)       // 4096 tiles
#define THREADS 256          // 8 warps x 16 cols
#define GRID 592             // 148 SMs x 4 CTAs
#define PITCH 132            // floats per k-row: conflict-free, 16B-aligned rows
#define KROWS 48
#define BUFF (KROWS * PITCH)
#define NTILE 9

typedef unsigned int u32;

__constant__ int c_kt[NTILE] = {0, 0, 0, 0, 0, 1, 1, 1, 2};
__constant__ int c_nt[NTILE] = {0, 1, 2, 3, 4, 2, 3, 4, 4};

static __device__ __forceinline__ void mma_f16(float* d, const u32* a, u32 b0, u32 b1) {
    asm volatile(
        "mma.sync.aligned.m16n8k16.row.col.f32.f16.f16.f32 "
        "{%0,%1,%2,%3}, {%4,%5,%6,%7}, {%8,%9}, {%0,%1,%2,%3};"
        : "+f"(d[0]), "+f"(d[1]), "+f"(d[2]), "+f"(d[3])
        : "r"(a[0]), "r"(a[1]), "r"(a[2]), "r"(a[3]), "r"(b0), "r"(b1));
}
static __device__ __forceinline__ u32 smem_u32(const void* p) {
    u32 a;
    asm("{ .reg .u64 t; cvta.to.shared.u64 t, %1; cvt.u32.u64 %0, t; }" : "=r"(a) : "l"(p));
    return a;
}
static __device__ __forceinline__ void cp16(u32 s, const void* g) {
    asm volatile("cp.async.cg.shared.global [%0], [%1], 16;" :: "r"(s), "l"(g) : "memory");
}
static __device__ __forceinline__ u32 packh2(float a, float b) {
    __half2 h = __floats2half2_rn(a, b);
    return *(u32*)&h;
}

__global__ __launch_bounds__(THREADS, 4)
void fwfm_main(const float* __restrict__ x,
               const float* __restrict__ W,
               float* __restrict__ out) {
    extern __shared__ float Xs[];   // 2 x [KROWS][PITCH] fp32

    const int tid = threadIdx.x;
    const int lane = tid & 31;
    const int g = lane >> 2, tq = lane & 3;
    const int cw = (tid >> 5) * 16;            // warp's 16 cols within tile
    const int ldrow = tid >> 5;                // load-phase row offset (warp id)
    const int ldcol = (lane) * 4;              // load-phase col (16B)

    // ---- issue tile-0 load immediately (hide everything below under it) ----
    int tile0 = blockIdx.x;
    {
        const float* src = x + (size_t)tile0 * NCOL;
        u32 dst = smem_u32(Xs);
#pragma unroll
        for (int it = 0; it < 5; ++it) {
            int row = it * 8 + ldrow;
            if (row < KF)
                cp16(dst + (u32)(row * PITCH + ldcol) * 4u,
                     src + (size_t)row * BD + ldcol);
        }
        asm volatile("cp.async.commit_group;" ::: "memory");
    }

    // ---- zero pad rows 39..47 of both buffers (cp.async never writes them) ----
    for (int i = tid; i < 2 * (KROWS - KF) * PITCH; i += THREADS) {
        int b = i / ((KROWS - KF) * PITCH);
        int r = i - b * ((KROWS - KF) * PITCH);
        Xs[b * BUFF + KF * PITCH + r] = 0.0f;
    }

    // ---- build B fragments from W in-register (L1/L2-cached scattered loads) ----
    u32 bf[NTILE][2];
#pragma unroll
    for (int t = 0; t < NTILE; ++t) {
        const int l = c_nt[t] * 8 + g;
        const int k0 = c_kt[t] * 16 + 2 * tq;
        float v[4];
#pragma unroll
        for (int dd = 0; dd < 4; ++dd) {
            int k = k0 + (dd >> 1) * 8 + (dd & 1);
            v[dd] = (l < KF && k < l) ? 0.5f * (__ldg(W + k * KF + l) + __ldg(W + l * KF + k))
                                      : 0.0f;
        }
        bf[t][0] = packh2(v[0], v[1]);
        bf[t][1] = packh2(v[2], v[3]);
    }

    // ---- grid-stride pipelined main loop ----
    int j = 0;
    for (int tile = tile0; tile < NT; tile += GRID, ++j) {
        const int nxt = tile + GRID;
        if (nxt < NT) {
            const float* src = x + (size_t)nxt * NCOL;
            u32 dst = smem_u32(Xs + ((j + 1) & 1) * BUFF);
#pragma unroll
            for (int it = 0; it < 5; ++it) {
                int row = it * 8 + ldrow;
                if (row < KF)
                    cp16(dst + (u32)(row * PITCH + ldcol) * 4u,
                         src + (size_t)row * BD + ldcol);
            }
            asm volatile("cp.async.commit_group;" ::: "memory");
            asm volatile("cp.async.wait_group 1;" ::: "memory");
        } else {
            asm volatile("cp.async.wait_group 0;" ::: "memory");
        }
        __syncthreads();

        const float* B = Xs + (j & 1) * BUFF;

        float d[5][4];
#pragma unroll
        for (int nt = 0; nt < 5; ++nt)
#pragma unroll
            for (int r = 0; r < 4; ++r) d[nt][r] = 0.0f;

#pragma unroll
        for (int kt = 0; kt < 3; ++kt) {
            const float* ap = B + (kt * 16 + 2 * tq) * PITCH + cw + g;
            u32 a[4];
            a[0] = packh2(ap[0], ap[PITCH]);
            a[1] = packh2(ap[8], ap[PITCH + 8]);
            a[2] = packh2(ap[8 * PITCH], ap[9 * PITCH]);
            a[3] = packh2(ap[8 * PITCH + 8], ap[9 * PITCH + 8]);
            if (kt == 0) {
#pragma unroll
                for (int q = 0; q < 5; ++q) mma_f16(d[q], a, bf[q][0], bf[q][1]);
            } else if (kt == 1) {
#pragma unroll
                for (int q = 5; q < 8; ++q) mma_f16(d[q - 3], a, bf[q][0], bf[q][1]);
            } else {
                mma_f16(d[4], a, bf[8][0], bf[8][1]);
            }
        }

        // Epilogue: out[c] = sum_l x[l,c]*T[l,c]; conflict-free fp32 LDS.
        {
            const float* xg = B + cw + g;
            float sg = 0.0f, sg8 = 0.0f;
#pragma unroll
            for (int nt = 0; nt < 5; ++nt) {
                const int l0 = nt * 8 + 2 * tq;
                sg = fmaf(xg[l0 * PITCH], d[nt][0], sg);
                sg = fmaf(xg[(l0 + 1) * PITCH], d[nt][1], sg);
                sg8 = fmaf(xg[l0 * PITCH + 8], d[nt][2], sg8);
                sg8 = fmaf(xg[(l0 + 1) * PITCH + 8], d[nt][3], sg8);
            }
            sg += __shfl_xor_sync(0xFFFFFFFFu, sg, 1);
            sg += __shfl_xor_sync(0xFFFFFFFFu, sg, 2);
            sg8 += __shfl_xor_sync(0xFFFFFFFFu, sg8, 1);
            sg8 += __shfl_xor_sync(0xFFFFFFFFu, sg8, 2);
            if (tq == 0) {
                float* o = out + (size_t)tile * NCOL + cw + g;
                o[0] = sg;
                o[8] = sg8;
            }
        }
        __syncthreads();   // buffer reuse fence
    }
}

extern "C" void kernel_launch(void* const* d_in, const int* in_sizes, int n_in,
                              void* d_out, int out_size) {
    const float* x = (const float*)d_in[0];   // [39, 8192, 64] fp32
    const float* W = (const float*)d_in[1];   // [39, 39] fp32
    float* out = (float*)d_out;               // [8192, 64] fp32

    static_assert(2 * BUFF * sizeof(float) < 227 * 1024, "smem");
    cudaFuncSetAttribute(fwfm_main, cudaFuncAttributeMaxDynamicSharedMemorySize,
                         2 * BUFF * (int)sizeof(float));

    fwfm_main<<<GRID, THREADS, 2 * BUFF * sizeof(float)>>>(x, W, out);
}

// round 11
// speedup vs baseline: 1.3902x; 1.3902x over previous
#include <cuda_runtime.h>
#include <cuda_fp16.h>
#include <cstdint>

// FwFM second-order via mma.sync fp16 + cp.async double-buffered pipeline.
//   out[c] = sum_l x[l,c] * T[l,c],  T: A = X^T (M=cols), B = L^T (N=l).
// R9 structure (static unrolled tile loop) + TILES=8/grid=512 (single wave)
// + B-fragment build folded into the main kernel (single launch).

#define KF 39
#define BD (8192 * 64)
#define NCOL 128            // columns per tile
#define THREADS 256         // 8 warps x 16 cols
#define TILES 8             // tiles per CTA (compile-time -> fully unrolled)
#define PITCH 132           // floats per k-row: conflict-free, rows 16B-aligned
#define KROWS 48
#define BUFF (KROWS * PITCH)
#define NTILE 9

typedef unsigned int u32;

__constant__ int c_kt[NTILE] = {0, 0, 0, 0, 0, 1, 1, 1, 2};
__constant__ int c_nt[NTILE] = {0, 1, 2, 3, 4, 2, 3, 4, 4};

static __device__ __forceinline__ void mma_f16(float* d, const u32* a, u32 b0, u32 b1) {
    asm volatile(
        "mma.sync.aligned.m16n8k16.row.col.f32.f16.f16.f32 "
        "{%0,%1,%2,%3}, {%4,%5,%6,%7}, {%8,%9}, {%0,%1,%2,%3};"
        : "+f"(d[0]), "+f"(d[1]), "+f"(d[2]), "+f"(d[3])
        : "r"(a[0]), "r"(a[1]), "r"(a[2]), "r"(a[3]), "r"(b0), "r"(b1));
}
static __device__ __forceinline__ u32 smem_u32(const void* p) {
    u32 a;
    asm("{ .reg .u64 t; cvta.to.shared.u64 t, %1; cvt.u32.u64 %0, t; }" : "=r"(a) : "l"(p));
    return a;
}
static __device__ __forceinline__ void cp16(u32 s, const void* g) {
    asm volatile("cp.async.cg.shared.global [%0], [%1], 16;" :: "r"(s), "l"(g) : "memory");
}
static __device__ __forceinline__ u32 packh2(float a, float b) {
    __half2 h = __floats2half2_rn(a, b);
    return *(u32*)&h;
}

__global__ __launch_bounds__(THREADS, 4)
void fwfm_main(const float* __restrict__ x,
               const float* __restrict__ W,
               float* __restrict__ out) {
    extern __shared__ float Xs[];   // 2 x [KROWS][PITCH] fp32

    const int tid = threadIdx.x;
    const size_t col_base = (size_t)blockIdx.x * (TILES * NCOL);
    const int ldrow = tid >> 5;            // load-phase row offset (warp id)
    const int ldcol = (tid & 31) * 4;      // load-phase col (16B chunk)

    // ---- issue tile-0 loads immediately (everything below hides under them) ----
    {
        const float* src0 = x + col_base;
        u32 dst0 = smem_u32(Xs);
#pragma unroll
        for (int it = 0; it < 5; ++it) {
            int row = it * 8 + ldrow;
            if (row < KF)
                cp16(dst0 + (u32)(row * PITCH + ldcol) * 4u,
                     src0 + (size_t)row * BD + ldcol);
        }
        asm volatile("cp.async.commit_group;" ::: "memory");
    }

    // ---- zero pad rows 39..47 of both buffers (cp.async never writes them) ----
    for (int i = tid; i < 2 * (KROWS - KF) * PITCH; i += THREADS) {
        int b = i / ((KROWS - KF) * PITCH);
        int r = i - b * ((KROWS - KF) * PITCH);
        Xs[b * BUFF + KF * PITCH + r] = 0.0f;
    }

    const int lane = tid & 31;
    const int g = lane >> 2, tq = lane & 3;
    const int cw = (tid >> 5) * 16;        // warp's 16 cols within tile

    // ---- build B fragments from W in-register (cached scattered loads) ----
    u32 bf[NTILE][2];
#pragma unroll
    for (int t = 0; t < NTILE; ++t) {
        const int l = c_nt[t] * 8 + g;
        const int k0 = c_kt[t] * 16 + 2 * tq;
        float v[4];
#pragma unroll
        for (int dd = 0; dd < 4; ++dd) {
            int k = k0 + (dd >> 1) * 8 + (dd & 1);
            v[dd] = (l < KF && k < l) ? 0.5f * (__ldg(W + k * KF + l) + __ldg(W + l * KF + k))
                                      : 0.0f;
        }
        bf[t][0] = packh2(v[0], v[1]);
        bf[t][1] = packh2(v[2], v[3]);
    }

#pragma unroll
    for (int t = 0; t < TILES; ++t) {
        if (t + 1 < TILES) {
            const float* srcn = x + col_base + (size_t)(t + 1) * NCOL;
            u32 dstn = smem_u32(Xs + ((t + 1) & 1) * BUFF);
#pragma unroll
            for (int it = 0; it < 5; ++it) {
                int row = it * 8 + ldrow;
                if (row < KF)
                    cp16(dstn + (u32)(row * PITCH + ldcol) * 4u,
                         srcn + (size_t)row * BD + ldcol);
            }
            asm volatile("cp.async.commit_group;" ::: "memory");
            asm volatile("cp.async.wait_group 1;" ::: "memory");
        } else {
            asm volatile("cp.async.wait_group 0;" ::: "memory");
        }
        __syncthreads();

        const float* B = Xs + (t & 1) * BUFF;

        float d[5][4];
#pragma unroll
        for (int nt = 0; nt < 5; ++nt)
#pragma unroll
            for (int r = 0; r < 4; ++r) d[nt][r] = 0.0f;

#pragma unroll
        for (int kt = 0; kt < 3; ++kt) {
            // A fragment from fp32 [k][col]: rows kt*16+2tq(+1,+8,+9), cols cw+g(+8).
            const float* ap = B + (kt * 16 + 2 * tq) * PITCH + cw + g;
            u32 a[4];
            a[0] = packh2(ap[0], ap[PITCH]);
            a[1] = packh2(ap[8], ap[PITCH + 8]);
            a[2] = packh2(ap[8 * PITCH], ap[9 * PITCH]);
            a[3] = packh2(ap[8 * PITCH + 8], ap[9 * PITCH + 8]);
            if (kt == 0) {
#pragma unroll
                for (int q = 0; q < 5; ++q) mma_f16(d[q], a, bf[q][0], bf[q][1]);
            } else if (kt == 1) {
#pragma unroll
                for (int q = 5; q < 8; ++q) mma_f16(d[q - 3], a, bf[q][0], bf[q][1]);
            } else {
                mma_f16(d[4], a, bf[8][0], bf[8][1]);
            }
        }

        // Epilogue: out[c] = sum_l x[l,c]*T[l,c]; conflict-free fp32 LDS.
        {
            const float* xg = B + cw + g;      // element l at xg[l*PITCH]
            float sg = 0.0f, sg8 = 0.0f;
#pragma unroll
            for (int nt = 0; nt < 5; ++nt) {
                const int l0 = nt * 8 + 2 * tq;
                sg = fmaf(xg[l0 * PITCH], d[nt][0], sg);
                sg = fmaf(xg[(l0 + 1) * PITCH], d[nt][1], sg);
                sg8 = fmaf(xg[l0 * PITCH + 8], d[nt][2], sg8);
                sg8 = fmaf(xg[(l0 + 1) * PITCH + 8], d[nt][3], sg8);
            }
            sg += __shfl_xor_sync(0xFFFFFFFFu, sg, 1);
            sg += __shfl_xor_sync(0xFFFFFFFFu, sg, 2);
            sg8 += __shfl_xor_sync(0xFFFFFFFFu, sg8, 1);
            sg8 += __shfl_xor_sync(0xFFFFFFFFu, sg8, 2);
            if (tq == 0) {
                float* o = out + col_base + (size_t)t * NCOL + cw + g;
                o[0] = sg;
                o[8] = sg8;
            }
        }
        __syncthreads();   // buffer reuse fence
    }
}

extern "C" void kernel_launch(void* const* d_in, const int* in_sizes, int n_in,
                              void* d_out, int out_size) {
    const float* x = (const float*)d_in[0];   // [39, 8192, 64] fp32
    const float* W = (const float*)d_in[1];   // [39, 39] fp32
    float* out = (float*)d_out;               // [8192, 64] fp32

    static_assert(2 * BUFF * sizeof(float) < 227 * 1024, "smem");
    cudaFuncSetAttribute(fwfm_main, cudaFuncAttributeMaxDynamicSharedMemorySize,
                         2 * BUFF * (int)sizeof(float));

    fwfm_main<<<BD / (TILES * NCOL), THREADS, 2 * BUFF * sizeof(float)>>>(x, W, out);
}

// round 14
// speedup vs baseline: 1.4615x; 1.0513x over previous
#include <cuda_runtime.h>
#include <cuda_fp16.h>
#include <cstdint>

// FwFM second-order via mma.sync fp16 + cp.async double-buffered pipeline.
//   out[c] = sum_l x[l,c] * T[l,c],  T: A = X^T (M=cols), B = L^T (N=l).
// Small-CTA variant: 128 threads / 64-col tiles, 8 CTAs/SM, grid=1024 -> one
// balanced wave with 1024 independent cp.async pipelines.

#define KF 39
#define BD (8192 * 64)
#define NCOL 64             // columns per tile
#define THREADS 128         // 4 warps x 16 cols
#define TILES 8             // tiles per CTA (compile-time -> fully unrolled)
#define PITCH 68            // floats per k-row: conflict-free, rows 16B-aligned
#define KROWS 48
#define BUFF (KROWS * PITCH)
#define NTILE 9

typedef unsigned int u32;

__constant__ int c_kt[NTILE] = {0, 0, 0, 0, 0, 1, 1, 1, 2};
__constant__ int c_nt[NTILE] = {0, 1, 2, 3, 4, 2, 3, 4, 4};

static __device__ __forceinline__ void mma_f16(float* d, const u32* a, u32 b0, u32 b1) {
    asm volatile(
        "mma.sync.aligned.m16n8k16.row.col.f32.f16.f16.f32 "
        "{%0,%1,%2,%3}, {%4,%5,%6,%7}, {%8,%9}, {%0,%1,%2,%3};"
        : "+f"(d[0]), "+f"(d[1]), "+f"(d[2]), "+f"(d[3])
        : "r"(a[0]), "r"(a[1]), "r"(a[2]), "r"(a[3]), "r"(b0), "r"(b1));
}
static __device__ __forceinline__ u32 smem_u32(const void* p) {
    u32 a;
    asm("{ .reg .u64 t; cvta.to.shared.u64 t, %1; cvt.u32.u64 %0, t; }" : "=r"(a) : "l"(p));
    return a;
}
static __device__ __forceinline__ void cp16(u32 s, const void* g) {
    asm volatile("cp.async.cg.shared.global [%0], [%1], 16;" :: "r"(s), "l"(g) : "memory");
}
static __device__ __forceinline__ u32 packh2(float a, float b) {
    __half2 h = __floats2half2_rn(a, b);
    return *(u32*)&h;
}

__global__ __launch_bounds__(THREADS, 8)
void fwfm_main(const float* __restrict__ x,
               const float* __restrict__ W,
               float* __restrict__ out) {
    extern __shared__ float Xs[];   // 2 x [KROWS][PITCH] fp32

    const int tid = threadIdx.x;
    const size_t col_base = (size_t)blockIdx.x * (TILES * NCOL);
    const int ldrow = tid >> 4;            // 0..7: row offset within 8-row sweep
    const int ldcol = (tid & 15) * 4;      // 16B chunk within 64-col row

    // ---- issue tile-0 loads immediately ----
    {
        const float* src0 = x + col_base;
        u32 dst0 = smem_u32(Xs);
#pragma unroll
        for (int it = 0; it < 5; ++it) {
            int row = it * 8 + ldrow;
            if (row < KF)
                cp16(dst0 + (u32)(row * PITCH + ldcol) * 4u,
                     src0 + (size_t)row * BD + ldcol);
        }
        asm volatile("cp.async.commit_group;" ::: "memory");
    }

    // ---- zero pad rows 39..47 of both buffers ----
    for (int i = tid; i < 2 * (KROWS - KF) * PITCH; i += THREADS) {
        int b = i / ((KROWS - KF) * PITCH);
        int r = i - b * ((KROWS - KF) * PITCH);
        Xs[b * BUFF + KF * PITCH + r] = 0.0f;
    }

    const int lane = tid & 31;
    const int g = lane >> 2, tq = lane & 3;
    const int cw = (tid >> 5) * 16;        // warp's 16 cols within 64-col tile

    // ---- build B fragments from W in-register (cached scattered loads) ----
    u32 bf[NTILE][2];
#pragma unroll
    for (int t = 0; t < NTILE; ++t) {
        const int l = c_nt[t] * 8 + g;
        const int k0 = c_kt[t] * 16 + 2 * tq;
        float v[4];
#pragma unroll
        for (int dd = 0; dd < 4; ++dd) {
            int k = k0 + (dd >> 1) * 8 + (dd & 1);
            v[dd] = (l < KF && k < l) ? 0.5f * (__ldg(W + k * KF + l) + __ldg(W + l * KF + k))
                                      : 0.0f;
        }
        bf[t][0] = packh2(v[0], v[1]);
        bf[t][1] = packh2(v[2], v[3]);
    }

#pragma unroll
    for (int t = 0; t < TILES; ++t) {
        if (t + 1 < TILES) {
            const float* srcn = x + col_base + (size_t)(t + 1) * NCOL;
            u32 dstn = smem_u32(Xs + ((t + 1) & 1) * BUFF);
#pragma unroll
            for (int it = 0; it < 5; ++it) {
                int row = it * 8 + ldrow;
                if (row < KF)
                    cp16(dstn + (u32)(row * PITCH + ldcol) * 4u,
                         srcn + (size_t)row * BD + ldcol);
            }
            asm volatile("cp.async.commit_group;" ::: "memory");
            asm volatile("cp.async.wait_group 1;" ::: "memory");
        } else {
            asm volatile("cp.async.wait_group 0;" ::: "memory");
        }
        __syncthreads();

        const float* B = Xs + (t & 1) * BUFF;

        float d[5][4];
#pragma unroll
        for (int nt = 0; nt < 5; ++nt)
#pragma unroll
            for (int r = 0; r < 4; ++r) d[nt][r] = 0.0f;

#pragma unroll
        for (int kt = 0; kt < 3; ++kt) {
            // A fragment from fp32 [k][col]: rows kt*16+2tq(+1,+8,+9), cols cw+g(+8).
            const float* ap = B + (kt * 16 + 2 * tq) * PITCH + cw + g;
            u32 a[4];
            a[0] = packh2(ap[0], ap[PITCH]);
            a[1] = packh2(ap[8], ap[PITCH + 8]);
            a[2] = packh2(ap[8 * PITCH], ap[9 * PITCH]);
            a[3] = packh2(ap[8 * PITCH + 8], ap[9 * PITCH + 8]);
            if (kt == 0) {
#pragma unroll
                for (int q = 0; q < 5; ++q) mma_f16(d[q], a, bf[q][0], bf[q][1]);
            } else if (kt == 1) {
#pragma unroll
                for (int q = 5; q < 8; ++q) mma_f16(d[q - 3], a, bf[q][0], bf[q][1]);
            } else {
                mma_f16(d[4], a, bf[8][0], bf[8][1]);
            }
        }

        // Epilogue: out[c] = sum_l x[l,c]*T[l,c]; conflict-free fp32 LDS.
        {
            const float* xg = B + cw + g;      // element l at xg[l*PITCH]
            float sg = 0.0f, sg8 = 0.0f;
#pragma unroll
            for (int nt = 0; nt < 5; ++nt) {
                const int l0 = nt * 8 + 2 * tq;
                sg = fmaf(xg[l0 * PITCH], d[nt][0], sg);
                sg = fmaf(xg[(l0 + 1) * PITCH], d[nt][1], sg);
                sg8 = fmaf(xg[l0 * PITCH + 8], d[nt][2], sg8);
                sg8 = fmaf(xg[(l0 + 1) * PITCH + 8], d[nt][3], sg8);
            }
            sg += __shfl_xor_sync(0xFFFFFFFFu, sg, 1);
            sg += __shfl_xor_sync(0xFFFFFFFFu, sg, 2);
            sg8 += __shfl_xor_sync(0xFFFFFFFFu, sg8, 1);
            sg8 += __shfl_xor_sync(0xFFFFFFFFu, sg8, 2);
            if (tq == 0) {
                float* o = out + col_base + (size_t)t * NCOL + cw + g;
                o[0] = sg;
                o[8] = sg8;
            }
        }
        __syncthreads();   // buffer reuse fence
    }
}

extern "C" void kernel_launch(void* const* d_in, const int* in_sizes, int n_in,
                              void* d_out, int out_size) {
    const float* x = (const float*)d_in[0];   // [39, 8192, 64] fp32
    const float* W = (const float*)d_in[1];   // [39, 39] fp32
    float* out = (float*)d_out;               // [8192, 64] fp32

    static_assert(2 * BUFF * sizeof(float) * 8 <= 227 * 1024, "smem x occ8");
    cudaFuncSetAttribute(fwfm_main, cudaFuncAttributeMaxDynamicSharedMemorySize,
                         2 * BUFF * (int)sizeof(float));

    fwfm_main<<<BD / (TILES * NCOL), THREADS, 2 * BUFF * sizeof(float)>>>(x, W, out);
}